// round 8
// baseline (speedup 1.0000x reference)
#include <cuda_runtime.h>
#include <cuda_bf16.h>
#include <cstdint>
#include <math.h>

#define B_ 4
#define L_ 256
#define D_ 512
#define H_ 8
#define DK_ 64

typedef __nv_bfloat16 bf16;
typedef __nv_bfloat162 bf162;

// ---------------------------------------------------------------------------
// Scratch (allocation-free rule: __device__ globals)
// ---------------------------------------------------------------------------
__device__ float g_qh[B_*H_*L_*DK_];
__device__ float g_kh[B_*H_*L_*DK_];
__device__ float g_vh[B_*H_*L_*DK_];

__device__ __align__(16) bf16 g_Xhi[3*1024*512];   // q,k,v inputs [m][k]
__device__ __align__(16) bf16 g_Xlo[3*1024*512];
__device__ __align__(16) bf16 g_Whi[4*512*512];    // Wq,Wk,Wv,W0 TRANSPOSED [n][k]
__device__ __align__(16) bf16 g_Wlo[4*512*512];
__device__ __align__(16) bf16 g_ctx_hi[1024*512];  // attention context [m][k]
__device__ __align__(16) bf16 g_ctx_lo[1024*512];

// ---------------------------------------------------------------------------
__device__ __forceinline__ uint32_t smem_u32(const void* p) {
    uint32_t a;
    asm("{ .reg .u64 t; cvta.to.shared.u64 t, %1; cvt.u32.u64 %0, t; }" : "=r"(a) : "l"(p));
    return a;
}
__device__ __forceinline__ float tanh_fast(float x) {
    float y;
    asm("tanh.approx.f32 %0, %1;" : "=f"(y) : "f"(x));
    return y;
}
__device__ __forceinline__ void ldm_x4(uint32_t* r, uint32_t addr) {
    asm volatile("ldmatrix.sync.aligned.m8n8.x4.shared.b16 {%0,%1,%2,%3}, [%4];"
        : "=r"(r[0]), "=r"(r[1]), "=r"(r[2]), "=r"(r[3]) : "r"(addr));
}
__device__ __forceinline__ void mma_bf16(float* c, const uint32_t* a, const uint32_t* b) {
    asm volatile(
        "mma.sync.aligned.m16n8k16.row.col.f32.bf16.bf16.f32 "
        "{%0,%1,%2,%3}, {%4,%5,%6,%7}, {%8,%9}, {%0,%1,%2,%3};"
        : "+f"(c[0]), "+f"(c[1]), "+f"(c[2]), "+f"(c[3])
        : "r"(a[0]), "r"(a[1]), "r"(a[2]), "r"(a[3]), "r"(b[0]), "r"(b[1]));
}
__device__ __forceinline__ void split_bf(float x, bf16& hi, bf16& lo) {
    hi = __float2bfloat16_rn(x);
    lo = __float2bfloat16_rn(x - __bfloat162float(hi));
}

// ---------------------------------------------------------------------------
// One-time fp32 -> (hi,lo) bf16 converts
// ---------------------------------------------------------------------------
__global__ __launch_bounds__(256) void convert_x_kernel(
    const float* __restrict__ q, const float* __restrict__ k, const float* __restrict__ v)
{
    int z = blockIdx.y;
    const float* src = (z == 0) ? q : (z == 1 ? k : v);
    int i = (blockIdx.x * 256 + threadIdx.x) * 4;
    float4 x = *(const float4*)(src + i);
    bf16 h0, l0, h1, l1, h2, l2, h3, l3;
    split_bf(x.x, h0, l0); split_bf(x.y, h1, l1);
    split_bf(x.z, h2, l2); split_bf(x.w, h3, l3);
    size_t base = (size_t)z * (1024*512) + i;
    bf162* ph = (bf162*)&g_Xhi[base];
    bf162* pl = (bf162*)&g_Xlo[base];
    ph[0] = bf162(h0, h1); ph[1] = bf162(h2, h3);
    pl[0] = bf162(l0, l1); pl[1] = bf162(l2, l3);
}

// W [k][n] -> [n][k] transpose + hi/lo split.  block (32,8), grid (16,16,4)
__global__ __launch_bounds__(256) void convert_w_kernel(
    const float* __restrict__ Wq, const float* __restrict__ Wk,
    const float* __restrict__ Wv, const float* __restrict__ W0)
{
    __shared__ float tile[32][33];
    int z = blockIdx.z;
    const float* W = (z == 0) ? Wq : (z == 1 ? Wk : (z == 2 ? Wv : W0));
    int k0 = blockIdx.x * 32, n0 = blockIdx.y * 32;
    int tx = threadIdx.x, ty = threadIdx.y;
    #pragma unroll
    for (int it = 0; it < 4; it++)
        tile[ty + it * 8][tx] = W[(size_t)(k0 + ty + it * 8) * D_ + n0 + tx];
    __syncthreads();
    size_t zb = (size_t)z * (512*512);
    #pragma unroll
    for (int it = 0; it < 4; it++) {
        int nr = ty + it * 8;
        bf16 hi, lo;
        split_bf(tile[tx][nr], hi, lo);
        g_Whi[zb + (size_t)(n0 + nr) * D_ + k0 + tx] = hi;
        g_Wlo[zb + (size_t)(n0 + nr) * D_ + k0 + tx] = lo;
    }
}

// ---------------------------------------------------------------------------
// 3xBF16 tensor-core GEMM (unchanged from R7 winner)
// ---------------------------------------------------------------------------
#define SA 40
#define A_HALVES (128*SA)
#define B_HALVES (64*SA)
#define GEMM_BUF_H (2*A_HALVES + 2*B_HALVES)
#define GEMM_SMEM_BYTES (2*GEMM_BUF_H*2)

template<bool HEADSPLIT>
__device__ __forceinline__ void gemm_core(
    const bf16* __restrict__ Ahi_g, const bf16* __restrict__ Alo_g,
    const bf16* __restrict__ Bhi_g, const bf16* __restrict__ Blo_g,
    const float* __restrict__ bias, float* __restrict__ Y)
{
    extern __shared__ __align__(16) bf16 smh[];
    const int tid = threadIdx.x;
    const int lane = tid & 31, wid = tid >> 5;
    const int g = lane >> 2, t4 = lane & 3;
    const int warp_m = (wid & 3) * 32;
    const int warp_n = (wid >> 2) * 32;
    const int m0 = blockIdx.x * 128, n0 = blockIdx.y * 64;

    const int am = tid >> 1, ah = (tid & 1) * 16;
    const int bn = tid >> 2, bh = (tid & 3) * 8;
    const bf16* Asrc_h = Ahi_g + (size_t)(m0 + am) * D_ + ah;
    const bf16* Asrc_l = Alo_g + (size_t)(m0 + am) * D_ + ah;
    const bf16* Bsrc_h = Bhi_g + (size_t)(n0 + bn) * D_ + bh;
    const bf16* Bsrc_l = Blo_g + (size_t)(n0 + bn) * D_ + bh;

    float acc[2][4][4];
    #pragma unroll
    for (int i = 0; i < 2; i++)
        #pragma unroll
        for (int j = 0; j < 4; j++)
            #pragma unroll
            for (int c = 0; c < 4; c++) acc[i][j][c] = 0.0f;

    const int lrow = lane & 15;
    const int lk   = (lane >> 4) * 8;
    const int bln  = lane & 7;
    const int bseg = (lane >> 3) & 1;
    const int bhi16 = (lane >> 4);
    const uint32_t smem_base = smem_u32(smh);
    const uint32_t aoff0 = ((warp_m + lrow)      * SA + lk) * 2;
    const uint32_t aoff1 = ((warp_m + 16 + lrow) * SA + lk) * 2;
    const uint32_t boff0 = ((warp_n + bln)       * SA + bseg * 8) * 2 + bhi16 * (8 * SA * 2);
    const uint32_t boff1 = boff0 + 16 * SA * 2;

    uint4 rAh0, rAh1, rAl0, rAl1, rBh, rBl;
    rAh0 = *(const uint4*)(Asrc_h);  rAh1 = *(const uint4*)(Asrc_h + 8);
    rAl0 = *(const uint4*)(Asrc_l);  rAl1 = *(const uint4*)(Asrc_l + 8);
    rBh  = *(const uint4*)(Bsrc_h);  rBl  = *(const uint4*)(Bsrc_l);

    for (int s = 0; s < 16; s++) {
        const int buf = s & 1;
        bf16* Ah_s = smh + buf * GEMM_BUF_H;
        bf16* Al_s = Ah_s + A_HALVES;
        bf16* Bh_s = Al_s + A_HALVES;
        bf16* Bl_s = Bh_s + B_HALVES;

        *(uint4*)&Ah_s[am * SA + ah]     = rAh0;
        *(uint4*)&Ah_s[am * SA + ah + 8] = rAh1;
        *(uint4*)&Al_s[am * SA + ah]     = rAl0;
        *(uint4*)&Al_s[am * SA + ah + 8] = rAl1;
        *(uint4*)&Bh_s[bn * SA + bh] = rBh;
        *(uint4*)&Bl_s[bn * SA + bh] = rBl;
        __syncthreads();

        if (s < 15) {
            const int off = (s + 1) * 32;
            rAh0 = *(const uint4*)(Asrc_h + off); rAh1 = *(const uint4*)(Asrc_h + off + 8);
            rAl0 = *(const uint4*)(Asrc_l + off); rAl1 = *(const uint4*)(Asrc_l + off + 8);
            rBh  = *(const uint4*)(Bsrc_h + off); rBl  = *(const uint4*)(Bsrc_l + off);
        }

        const uint32_t base = smem_base + (uint32_t)(buf * GEMM_BUF_H * 2);
        const uint32_t aBh = base;
        const uint32_t aBl = base + A_HALVES * 2;
        const uint32_t bBh = base + 2 * A_HALVES * 2;
        const uint32_t bBl = bBh + B_HALVES * 2;

        #pragma unroll
        for (int kk = 0; kk < 2; kk++) {
            const uint32_t ko = kk * 32;
            uint32_t Ah0[4], Ah1[4], Al0[4], Al1[4];
            uint32_t Bh0[4], Bh1[4], Bl0[4], Bl1[4];
            ldm_x4(Ah0, aBh + aoff0 + ko);
            ldm_x4(Ah1, aBh + aoff1 + ko);
            ldm_x4(Al0, aBl + aoff0 + ko);
            ldm_x4(Al1, aBl + aoff1 + ko);
            ldm_x4(Bh0, bBh + boff0 + ko);
            ldm_x4(Bh1, bBh + boff1 + ko);
            ldm_x4(Bl0, bBl + boff0 + ko);
            ldm_x4(Bl1, bBl + boff1 + ko);

            #pragma unroll
            for (int i = 0; i < 2; i++) {
                uint32_t* ahp = i ? Ah1 : Ah0;
                uint32_t* alp = i ? Al1 : Al0;
                #pragma unroll
                for (int j = 0; j < 4; j++) {
                    uint32_t* bhp = (j < 2) ? Bh0 : Bh1;
                    uint32_t* blp = (j < 2) ? Bl0 : Bl1;
                    uint32_t bhf[2] = { bhp[(j & 1) * 2], bhp[(j & 1) * 2 + 1] };
                    uint32_t blf[2] = { blp[(j & 1) * 2], blp[(j & 1) * 2 + 1] };
                    mma_bf16(acc[i][j], ahp, bhf);
                    mma_bf16(acc[i][j], ahp, blf);
                    mma_bf16(acc[i][j], alp, bhf);
                }
            }
        }
    }

    #pragma unroll
    for (int i = 0; i < 2; i++) {
        #pragma unroll
        for (int j = 0; j < 4; j++) {
            int col_loc = warp_n + (j >> 1) * 16 + (j & 1) * 8 + 2 * t4;
            int cng = n0 + col_loc;
            float b0 = bias[cng], b1 = bias[cng + 1];
            int r0 = m0 + warp_m + i * 16 + g;
            int r1 = r0 + 8;
            float2 v0 = make_float2(acc[i][j][0] + b0, acc[i][j][1] + b1);
            float2 v1 = make_float2(acc[i][j][2] + b0, acc[i][j][3] + b1);
            if (HEADSPLIT) {
                int h = blockIdx.y;
                float* d0 = Y + ((size_t)((r0 >> 8) * H_ + h) * L_ + (r0 & 255)) * DK_ + col_loc;
                float* d1 = Y + ((size_t)((r1 >> 8) * H_ + h) * L_ + (r1 & 255)) * DK_ + col_loc;
                *(float2*)d0 = v0;
                *(float2*)d1 = v1;
            } else {
                *(float2*)(Y + (size_t)r0 * D_ + cng) = v0;
                *(float2*)(Y + (size_t)r1 * D_ + cng) = v1;
            }
        }
    }
}

__global__ __launch_bounds__(256, 2) void qkv_mma_kernel(
    const float* __restrict__ bq, const float* __restrict__ bk, const float* __restrict__ bv)
{
    int z = blockIdx.z;
    const float* bias = (z == 0) ? bq : (z == 1 ? bk : bv);
    float* out = (z == 0) ? g_qh : (z == 1 ? g_kh : g_vh);
    gemm_core<true>(g_Xhi + (size_t)z * (1024*512), g_Xlo + (size_t)z * (1024*512),
                    g_Whi + (size_t)z * (512*512),  g_Wlo + (size_t)z * (512*512),
                    bias, out);
}

__global__ __launch_bounds__(256, 2) void out_mma_kernel(
    const float* __restrict__ b0, float* __restrict__ Y)
{
    gemm_core<false>(g_ctx_hi, g_ctx_lo,
                     g_Whi + (size_t)3 * (512*512), g_Wlo + (size_t)3 * (512*512),
                     b0, Y);
}

// ---------------------------------------------------------------------------
// Fused Bahdanau attention, high-occupancy version.
// One CTA per (b, h, 16-row i-block): grid (16, 32) = 512 CTAs, 256 threads.
// SMEM ~39KB -> 4-5 CTAs/SM. V streamed from L2 (broadcast/coalesced).
// ---------------------------------------------------------------------------
#define IB 16
#define QS_STRIDE 18
#define KS_STRIDE 66
#define S_STRIDE 260
#define ATTN_SMEM_FLOATS (64*QS_STRIDE + 64*KS_STRIDE + IB*S_STRIDE + 64 + IB)
#define ATTN_SMEM_BYTES  (ATTN_SMEM_FLOATS * 4)

__global__ __launch_bounds__(256) void attn_kernel(
    const int* __restrict__ mask, const float* __restrict__ vp)
{
    extern __shared__ __align__(16) float sm[];
    float* Qs   = sm;                        // [d][i]  64 x 18
    float* Ks   = Qs + 64 * QS_STRIDE;       // [d][j]  64 x 66
    float* S    = Ks + 64 * KS_STRIDE;       // [i][j]  16 x 260
    float* vps  = S + IB * S_STRIDE;         // 64
    float* rinv = vps + 64;                  // 16

    const int tid = threadIdx.x;
    const int bh = blockIdx.y;
    const int b = bh >> 3;
    const int h = bh & 7;
    const int i0 = blockIdx.x * IB;

    const float* qh  = g_qh + (size_t)(bh * L_ + i0) * DK_;
    const float* khp = g_kh + (size_t)bh * L_ * DK_;
    const float* vhp = g_vh + (size_t)bh * L_ * DK_;

    if (tid < 64) vps[tid] = vp[h * DK_ + tid];

    // Load Q transposed: thread (i = tid>>4, d0 = (tid&15)*4)
    {
        int i = tid >> 4, d0 = (tid & 15) * 4;
        float4 t = *(const float4*)&qh[(size_t)i * DK_ + d0];
        Qs[(d0 + 0) * QS_STRIDE + i] = t.x;
        Qs[(d0 + 1) * QS_STRIDE + i] = t.y;
        Qs[(d0 + 2) * QS_STRIDE + i] = t.z;
        Qs[(d0 + 3) * QS_STRIDE + i] = t.w;
    }

    const int ti = tid & 7;     // i pair: rows 2ti, 2ti+1
    const int tj = tid >> 3;    // j pair: cols 2tj, 2tj+1 (0..63)

    // ---- Scores: S[i][j] = sum_d vp[d]*tanh(q[i][d]+k[j][d]), 4 j-tiles ----
    for (int jb = 0; jb < 4; jb++) {
        __syncthreads();   // Ks consumers of prev tile done (first iter: Q/vps visible)
        {
            int j = tid >> 2, d0 = (tid & 3) * 16;
            const float* kr = khp + (size_t)(jb * 64 + j) * DK_;
            #pragma unroll
            for (int u = 0; u < 4; u++) {
                float4 t = *(const float4*)&kr[d0 + u * 4];
                Ks[(d0 + u * 4 + 0) * KS_STRIDE + j] = t.x;
                Ks[(d0 + u * 4 + 1) * KS_STRIDE + j] = t.y;
                Ks[(d0 + u * 4 + 2) * KS_STRIDE + j] = t.z;
                Ks[(d0 + u * 4 + 3) * KS_STRIDE + j] = t.w;
            }
        }
        __syncthreads();

        float acc[2][2] = {};
        #pragma unroll 4
        for (int d = 0; d < 64; d++) {
            float w = vps[d];
            float2 qv = *(const float2*)&Qs[d * QS_STRIDE + ti * 2];
            float2 kv = *(const float2*)&Ks[d * KS_STRIDE + tj * 2];
            acc[0][0] += w * tanh_fast(qv.x + kv.x);
            acc[0][1] += w * tanh_fast(qv.x + kv.y);
            acc[1][0] += w * tanh_fast(qv.y + kv.x);
            acc[1][1] += w * tanh_fast(qv.y + kv.y);
        }
        #pragma unroll
        for (int a = 0; a < 2; a++) {
            S[(ti * 2 + a) * S_STRIDE + jb * 64 + tj * 2 + 0] = acc[a][0];
            S[(ti * 2 + a) * S_STRIDE + jb * 64 + tj * 2 + 1] = acc[a][1];
        }
    }
    __syncthreads();

    // ---- Masked softmax: 8 warps x 2 rows, 8 cols per lane ----
    {
        int warp = tid >> 5, lane = tid & 31;
        #pragma unroll
        for (int r = 0; r < 2; r++) {
            int row = warp * 2 + r;
            const int* mrow = mask + ((size_t)b * L_ + i0 + row) * L_;
            float vals[8];
            float mmax = -3.4e38f;
            #pragma unroll
            for (int c8 = 0; c8 < 8; c8++) {
                int c = c8 * 32 + lane;
                float s = S[row * S_STRIDE + c];
                if (mrow[c] == 0) s = -1.0e9f;
                vals[c8] = s;
                mmax = fmaxf(mmax, s);
            }
            #pragma unroll
            for (int off = 16; off > 0; off >>= 1)
                mmax = fmaxf(mmax, __shfl_xor_sync(0xFFFFFFFFu, mmax, off));
            float sum = 0.0f;
            #pragma unroll
            for (int c8 = 0; c8 < 8; c8++) {
                float e = __expf(vals[c8] - mmax);
                S[row * S_STRIDE + c8 * 32 + lane] = e;
                sum += e;
            }
            #pragma unroll
            for (int off = 16; off > 0; off >>= 1)
                sum += __shfl_xor_sync(0xFFFFFFFFu, sum, off);
            if (lane == 0) rinv[row] = 1.0f / sum;
        }
    }
    __syncthreads();

    // ---- PV: stream V rows from global (L2-hot; broadcast across i-threads) ----
    {
        int i   = tid >> 4;          // 16 rows
        int seg = tid & 15;          // 16 x float4 = 64 dk
        const float* Vg = vhp + seg * 4;
        float o0 = 0, o1 = 0, o2 = 0, o3 = 0;
        const float* Srow = &S[i * S_STRIDE];
        #pragma unroll 4
        for (int j = 0; j < L_; j++) {
            float p = Srow[j];
            float4 v = *(const float4*)(Vg + (size_t)j * DK_);
            o0 += p * v.x; o1 += p * v.y; o2 += p * v.z; o3 += p * v.w;
        }
        float inv = rinv[i];
        o0 *= inv; o1 *= inv; o2 *= inv; o3 *= inv;
        size_t off = ((size_t)(b * L_ + i0 + i)) * D_ + h * DK_ + seg * 4;
        bf16 h0, l0, h1, l1, h2, l2, h3, l3;
        split_bf(o0, h0, l0); split_bf(o1, h1, l1);
        split_bf(o2, h2, l2); split_bf(o3, h3, l3);
        bf162* ph = (bf162*)&g_ctx_hi[off];
        bf162* pl = (bf162*)&g_ctx_lo[off];
        ph[0] = bf162(h0, h1); ph[1] = bf162(h2, h3);
        pl[0] = bf162(l0, l1); pl[1] = bf162(l2, l3);
    }
}

// ===========================================================================
extern "C" void kernel_launch(void* const* d_in, const int* in_sizes, int n_in,
                              void* d_out, int out_size)
{
    const float* q    = (const float*)d_in[0];
    const float* k    = (const float*)d_in[1];
    const float* v    = (const float*)d_in[2];
    const int*   mask = (const int*)  d_in[3];
    const float* Wq   = (const float*)d_in[4];
    const float* bq   = (const float*)d_in[5];
    const float* Wk   = (const float*)d_in[6];
    const float* bk   = (const float*)d_in[7];
    const float* Wv   = (const float*)d_in[8];
    const float* bv   = (const float*)d_in[9];
    const float* vp   = (const float*)d_in[10];
    const float* W0   = (const float*)d_in[11];
    const float* b0   = (const float*)d_in[12];
    float* out = (float*)d_out;

    static bool attr_set = false;
    if (!attr_set) {
        cudaFuncSetAttribute(attn_kernel,
                             cudaFuncAttributeMaxDynamicSharedMemorySize, ATTN_SMEM_BYTES);
        cudaFuncSetAttribute(qkv_mma_kernel,
                             cudaFuncAttributeMaxDynamicSharedMemorySize, GEMM_SMEM_BYTES);
        cudaFuncSetAttribute(out_mma_kernel,
                             cudaFuncAttributeMaxDynamicSharedMemorySize, GEMM_SMEM_BYTES);
        attr_set = true;
    }

    convert_x_kernel<<<dim3(512, 3), 256>>>(q, k, v);
    convert_w_kernel<<<dim3(16, 16, 4), dim3(32, 8)>>>(Wq, Wk, Wv, W0);
    qkv_mma_kernel<<<dim3(8, 8, 3), 256, GEMM_SMEM_BYTES>>>(bq, bk, bv);
    attn_kernel<<<dim3(16, 32), 256, ATTN_SMEM_BYTES>>>(mask, vp);
    out_mma_kernel<<<dim3(8, 8), 256, GEMM_SMEM_BYTES>>>(b0, out);
}